// round 12
// baseline (speedup 1.0000x reference)
#include <cuda_runtime.h>
#include <cuda_bf16.h>
#include <cstdint>
#include <math.h>

// Fixed problem dims
#define BB   128
#define TT   255
#define NN   256
#define HH   256
#define FH   1024
#define MM   (BB*TT)          // 32640

// Static device scratch (no allocations allowed)
__device__ float g_alpha[BB * NN];
__device__ float g_P[(size_t)MM * FH];   // 133.7 MB

// ---------------------------------------------------------------------------
// helpers
// ---------------------------------------------------------------------------
__device__ __forceinline__ uint32_t smem_u32(const void* p) {
    uint32_t a;
    asm("{ .reg .u64 t; cvta.to.shared.u64 t, %1; cvt.u32.u64 %0, t; }"
        : "=r"(a) : "l"(p));
    return a;
}
__device__ __forceinline__ uint32_t mapa_u32(uint32_t addr, uint32_t rank) {
    uint32_t r;
    asm("mapa.shared::cluster.u32 %0, %1, %2;" : "=r"(r) : "r"(addr), "r"(rank));
    return r;
}
__device__ __forceinline__ uint32_t ctarank() {
    uint32_t r;
    asm("mov.u32 %0, %%cluster_ctarank;" : "=r"(r));
    return r;
}
__device__ __forceinline__ void cluster_sync_() {
    asm volatile("barrier.cluster.arrive.aligned;" ::: "memory");
    asm volatile("barrier.cluster.wait.aligned;" ::: "memory");
}
__device__ __forceinline__ void ffma2(unsigned long long& d,
                                      unsigned long long a,
                                      unsigned long long b) {
    asm("fma.rn.f32x2 %0, %1, %2, %0;" : "+l"(d) : "l"(a), "l"(b));
}
__device__ __forceinline__ float pairsum(unsigned long long v) {
    float lo, hi;
    asm("mov.b64 {%0,%1}, %2;" : "=f"(lo), "=f"(hi) : "l"(v));
    return lo + hi;
}
__device__ __forceinline__ unsigned long long pack2(float a) {
    unsigned long long d;
    asm("mov.b64 %0, {%1,%1};" : "=l"(d) : "f"(a));
    return d;
}
__device__ __forceinline__ unsigned long long packab(float a, float b) {
    unsigned long long d;
    asm("mov.b64 %0, {%1,%2};" : "=l"(d) : "f"(a), "f"(b));
    return d;
}
__device__ __forceinline__ void unpack2(unsigned long long v, float& lo, float& hi) {
    asm("mov.b64 {%0,%1}, %2;" : "=f"(lo), "=f"(hi) : "l"(v));
}
__device__ __forceinline__ void mbar_init(uint32_t mbar, uint32_t count) {
    asm volatile("mbarrier.init.shared.b64 [%0], %1;" :: "r"(mbar), "r"(count)
                 : "memory");
}
__device__ __forceinline__ void mbar_arm_tx(uint32_t mbar, uint32_t tx) {
    asm volatile("mbarrier.arrive.expect_tx.shared.b64 _, [%0], %1;"
                 :: "r"(mbar), "r"(tx) : "memory");
}
__device__ __forceinline__ void mbar_wait_acq(uint32_t mbar, uint32_t parity) {
    uint32_t done;
    asm volatile(
        "{\n\t.reg .pred P;\n\t"
        "mbarrier.try_wait.parity.acquire.cluster.shared::cta.b64 P, [%1], %2;\n\t"
        "selp.b32 %0, 1, 0, P;\n\t}"
        : "=r"(done) : "r"(mbar), "r"(parity) : "memory");
    while (!done) {
        asm volatile(
            "{\n\t.reg .pred P;\n\t"
            "mbarrier.try_wait.parity.acquire.cluster.shared::cta.b64 P, [%1], %2, 0x989680;\n\t"
            "selp.b32 %0, 1, 0, P;\n\t}"
            : "=r"(done) : "r"(mbar), "r"(parity) : "memory");
    }
}
__device__ __forceinline__ void bulk_dsmem(uint32_t dst_remote, uint32_t src_local,
                                           uint32_t bytes, uint32_t remote_mbar) {
    asm volatile(
        "cp.async.bulk.shared::cluster.shared::cta.mbarrier::complete_tx::bytes "
        "[%0], [%1], %2, [%3];"
        :: "r"(dst_remote), "r"(src_local), "r"(bytes), "r"(remote_mbar)
        : "memory");
}
__device__ __forceinline__ void fence_async_proxy() {
    asm volatile("fence.proxy.async.shared::cta;" ::: "memory");
}
__device__ __forceinline__ float sigf(float x) {
    return __fdividef(1.0f, 1.0f + __expf(-x));
}
__device__ __forceinline__ float tanh_fast(float x) {
    float e = __expf(-2.0f * x);
    return __fdividef(1.0f - e, 1.0f + e);
}

// ---------------------------------------------------------------------------
// K1: alpha[b,n] = softmax_n( b_attn + sum_t X[b,t,n] * Wa[2H+t] )
// ---------------------------------------------------------------------------
__global__ __launch_bounds__(256) void k_alpha(const float* __restrict__ X,
                                               const float* __restrict__ Wa,
                                               const float* __restrict__ ba) {
    __shared__ float was[TT];
    __shared__ float red[256];
    const int b = blockIdx.x, n = threadIdx.x;
    if (n < TT) was[n] = Wa[2 * HH + n];
    __syncthreads();

    const float* xb = X + (size_t)b * TT * NN + n;
    float acc = ba[0];
#pragma unroll 5
    for (int t = 0; t < TT; ++t) acc = fmaf(xb[(size_t)t * NN], was[t], acc);

    red[n] = acc; __syncthreads();
    for (int s = 128; s > 0; s >>= 1) {
        if (n < s) red[n] = fmaxf(red[n], red[n + s]);
        __syncthreads();
    }
    const float mx = red[0]; __syncthreads();
    const float e = expf(acc - mx);
    red[n] = e; __syncthreads();
    for (int s = 128; s > 0; s >>= 1) {
        if (n < s) red[n] += red[n + s];
        __syncthreads();
    }
    g_alpha[b * NN + n] = e / red[0];
}

// ---------------------------------------------------------------------------
// K2: X_tilde = alpha * X  ->  d_out[0 : MM*NN)
// ---------------------------------------------------------------------------
__global__ __launch_bounds__(256) void k_xtilde(const float* __restrict__ X,
                                                float* __restrict__ out) {
    const int idx = blockIdx.x * 256 + threadIdx.x;          // < MM*NN/4
    const float4 x = ((const float4*)X)[idx];
    const int b   = idx / (TT * NN / 4);
    const int rem = idx - b * (TT * NN / 4);
    const int n4  = rem & (NN / 4 - 1);
    const float4 a = ((const float4*)g_alpha)[b * (NN / 4) + n4];
    float4 o;
    o.x = x.x * a.x; o.y = x.y * a.y; o.z = x.z * a.z; o.w = x.w * a.w;
    ((float4*)out)[idx] = o;
}

// ---------------------------------------------------------------------------
// K3: P = X_tilde @ W_lstm + b_lstm   (M=32640, Ncols=1024, K=256) fp32
// 128x128 tile, 256 threads, 8x8 microtile, fma.rn.f32x2,
// register double-buffered global loads.
// ---------------------------------------------------------------------------
__global__ __launch_bounds__(256) void k_gemm(const float* __restrict__ A,
                                              const float* __restrict__ W,
                                              const float* __restrict__ bias) {
    __shared__ float As[16 * 132];
    __shared__ float Bs[16 * 132];
    const int tx = threadIdx.x & 15;
    const int ty = threadIdx.x >> 4;
    const int m0 = blockIdx.y * 128;
    const int c0 = blockIdx.x * 128;

    unsigned long long acc2[8][4];
#pragma unroll
    for (int i = 0; i < 8; ++i)
#pragma unroll
        for (int j = 0; j < 4; ++j) acc2[i][j] = 0ull;

    float4 pa[2], pb[2];
#pragma unroll
    for (int i = 0; i < 2; ++i) {
        const int id = threadIdx.x + 256 * i;
        pa[i] = *(const float4*)(A + (size_t)(m0 + (id >> 2)) * 256 + 4 * (id & 3));
        pb[i] = *(const float4*)(W + (size_t)(id >> 5) * 1024 + c0 + 4 * (id & 31));
    }

    for (int kk0 = 0; kk0 < 256; kk0 += 16) {
#pragma unroll
        for (int i = 0; i < 2; ++i) {               // store staged tiles
            const int id = threadIdx.x + 256 * i;
            const int q = id & 3, row = id >> 2;
            As[(4 * q + 0) * 132 + row] = pa[i].x;
            As[(4 * q + 1) * 132 + row] = pa[i].y;
            As[(4 * q + 2) * 132 + row] = pa[i].z;
            As[(4 * q + 3) * 132 + row] = pa[i].w;
            const int c4 = id & 31, k = id >> 5;
            *(float4*)(Bs + k * 132 + 4 * c4) = pb[i];
        }
        __syncthreads();
        if (kk0 + 16 < 256) {                       // prefetch next tiles
#pragma unroll
            for (int i = 0; i < 2; ++i) {
                const int id = threadIdx.x + 256 * i;
                pa[i] = *(const float4*)(A + (size_t)(m0 + (id >> 2)) * 256 +
                                         kk0 + 16 + 4 * (id & 3));
                pb[i] = *(const float4*)(W + (size_t)(kk0 + 16 + (id >> 5)) * 1024 +
                                         c0 + 4 * (id & 31));
            }
        }
#pragma unroll
        for (int kk = 0; kk < 16; ++kk) {
            const float4 a0 = *(const float4*)(As + kk * 132 + 4 * ty);
            const float4 a1 = *(const float4*)(As + kk * 132 + 64 + 4 * ty);
            const ulonglong2 bq0 = *(const ulonglong2*)(Bs + kk * 132 + 4 * tx);
            const ulonglong2 bq1 = *(const ulonglong2*)(Bs + kk * 132 + 64 + 4 * tx);
            const float av[8] = {a0.x, a0.y, a0.z, a0.w, a1.x, a1.y, a1.z, a1.w};
#pragma unroll
            for (int i = 0; i < 8; ++i) {
                const unsigned long long ad = pack2(av[i]);
                ffma2(acc2[i][0], ad, bq0.x);
                ffma2(acc2[i][1], ad, bq0.y);
                ffma2(acc2[i][2], ad, bq1.x);
                ffma2(acc2[i][3], ad, bq1.y);
            }
        }
        __syncthreads();
    }
#pragma unroll
    for (int i = 0; i < 8; ++i) {
        const int row = (i < 4) ? (4 * ty + i) : (64 + 4 * ty + (i - 4));
        float* p = g_P + (size_t)(m0 + row) * 1024 + c0;
        float4 o0, o1;
        float lo, hi;
        unpack2(acc2[i][0], lo, hi);
        o0.x = lo + bias[c0 + 4 * tx + 0];
        o0.y = hi + bias[c0 + 4 * tx + 1];
        unpack2(acc2[i][1], lo, hi);
        o0.z = lo + bias[c0 + 4 * tx + 2];
        o0.w = hi + bias[c0 + 4 * tx + 3];
        unpack2(acc2[i][2], lo, hi);
        o1.x = lo + bias[c0 + 64 + 4 * tx + 0];
        o1.y = hi + bias[c0 + 64 + 4 * tx + 1];
        unpack2(acc2[i][3], lo, hi);
        o1.z = lo + bias[c0 + 64 + 4 * tx + 2];
        o1.w = hi + bias[c0 + 64 + 4 * tx + 3];
        *(float4*)(p + 4 * tx) = o0;
        *(float4*)(p + 64 + 4 * tx) = o1;
    }
}

// ---------------------------------------------------------------------------
// K4 v7: LSTM recurrence — TWO pipelined batch groups per cluster.
// 16 clusters x 8 CTAs, 512 threads. Cluster owns 8 batches: group A = 0..3,
// group B = 4..7, each with its own h buffers / mbarriers / red buffer / c.
// Per step: waitA,fmaA,sync,ownerA+sendA, waitB,fmaB,sync,ownerB+sendB —
// each group's DSMEM flight + skew hides under the other group's compute.
// U loaded DIRECTLY gmem->registers (no smem staging; smem ~36KB).
// red layout [slot=b*4+KQ][col]: all STS/LDS conflict-free.
// ---------------------------------------------------------------------------
#define HBA_OFF   0                       // [2][8 ranks][128]  = 2048 fl
#define HBB_OFF   2048                    // [2][8 ranks][128]  = 2048 fl
#define STGA_OFF  4096                    // [2][128]           = 256 fl
#define STGB_OFF  4352                    // [2][128]           = 256 fl
#define REDA_OFF  4608                    // [16][128]          = 2048 fl
#define REDB_OFF  6656                    // [16][128]          = 2048 fl
#define MBAR_OFF  8704                    // 4 x u64            = 8 fl
#define SMEM_FLOATS 8712
#define SMEM_BYTES  (SMEM_FLOATS * 4)     // 34,848 B
#define TX_STEP   4096                    // 8 ranks x 512B per group per step

__global__ __launch_bounds__(512, 1) __cluster_dims__(8, 1, 1)
void k_lstm(const float* __restrict__ X, const float* __restrict__ U,
            float* __restrict__ out_enc) {
    extern __shared__ float sm[];
    float* hbA  = sm + HBA_OFF;
    float* hbB  = sm + HBB_OFF;
    float* stgA = sm + STGA_OFF;
    float* stgB = sm + STGB_OFF;
    float* redA = sm + REDA_OFF;
    float* redB = sm + REDB_OFF;

    const int rank = (int)ctarank();                 // 0..7
    const int b0   = (blockIdx.x >> 3) * 8;
    const int tid  = threadIdx.x;
    const int col  = tid & 127;                      // gate-col 0..127
    const int KQ   = tid >> 7;                       // k quarter 0..3
    const int ob   = tid >> 5;                       // owner batch 0..3 (tid<128)
    const int ou   = tid & 31;                       // owner unit 0..31
    const int jgo  = rank * 32 + ou;

    const uint32_t smb = smem_u32(sm);
    const uint32_t mbar0 = smb + MBAR_OFF * 4;       // A0,A1,B0,B1 at +0,8,16,24

    // ---- U slice direct to registers (coalesced: 32 consecutive cols/warp)
    const int g  = col >> 5, jr = col & 31;
    const int gcol = g * 256 + rank * 32 + jr;
    ulonglong2 u2[16];
    {
        const float* Ub = U + (size_t)(KQ * 64) * 1024 + gcol;
#pragma unroll
        for (int i = 0; i < 16; ++i) {
            const float a0 = Ub[(4 * i + 0) * 1024];
            const float a1 = Ub[(4 * i + 1) * 1024];
            const float a2 = Ub[(4 * i + 2) * 1024];
            const float a3 = Ub[(4 * i + 3) * 1024];
            u2[i].x = packab(a0, a1);
            u2[i].y = packab(a2, a3);
        }
    }

    // ---- init h buffers (h0 = c0 = X[b,0,0]) and mbarriers
    for (int idx = tid; idx < 1024; idx += 512) {
        const int b = (idx >> 5) & 3;
        hbA[idx] = X[(size_t)(b0 + b) * TT * NN];
        hbB[idx] = X[(size_t)(b0 + 4 + b) * TT * NN];
    }
    if (tid == 0) {
#pragma unroll
        for (int i = 0; i < 4; ++i) {
            mbar_init(mbar0 + 8 * i, 1);
            mbar_arm_tx(mbar0 + 8 * i, TX_STEP);
        }
    }
    __syncthreads();
    cluster_sync_();    // barriers + buffer0 visible cluster-wide (once)

    float cA = 0.f, cB = 0.f;
    float piA = 0, pfA = 0, pgA = 0, poA = 0, piB = 0, pfB = 0, pgB = 0, poB = 0;
    const float *PbA = 0, *PbB = 0;
    float *ObA = 0, *ObB = 0;
    if (tid < 128) {
        cA = X[(size_t)(b0 + ob) * TT * NN];
        cB = X[(size_t)(b0 + 4 + ob) * TT * NN];
        PbA = g_P + (size_t)(b0 + ob) * TT * 1024 + jgo;
        PbB = g_P + (size_t)(b0 + 4 + ob) * TT * 1024 + jgo;
        ObA = out_enc + (size_t)(b0 + ob) * TT * HH + jgo;
        ObB = out_enc + (size_t)(b0 + 4 + ob) * TT * HH + jgo;
        piA = PbA[0]; pfA = PbA[256]; pgA = PbA[512]; poA = PbA[768];
        piB = PbB[0]; pfB = PbB[256]; pgB = PbB[512]; poB = PbB[768];
    }
    uint32_t phA0 = 0, phA1 = 0, phB0 = 0, phB1 = 0;

    for (int t = 0; t < TT; ++t) {
        const int cb = t & 1, nb = 1 - cb;

        // ================= GROUP A =================
        float npi = 0, npf = 0, npg = 0, npo = 0;
        if (tid < 128 && t + 1 < TT) {
            const float* pr = PbA + (size_t)(t + 1) * 1024;
            npi = pr[0]; npf = pr[256]; npg = pr[512]; npo = pr[768];
        }
        if (t > 0) {
            const uint32_t mb = mbar0 + 8 * cb;
            if (cb) { mbar_wait_acq(mb, phA1); phA1 ^= 1; }
            else    { mbar_wait_acq(mb, phA0); phA0 ^= 1; }
            if (tid == 0 && t + 2 < TT) mbar_arm_tx(mb, TX_STEP);
        }
        {
            const float* ha = hbA + cb * 1024;
            unsigned long long acc[4] = {0ull, 0ull, 0ull, 0ull};
#pragma unroll
            for (int ch = 0; ch < 16; ++ch) {
                const int k0 = KQ * 64 + 4 * ch;
                const float* hp = ha + ((k0 >> 5) << 7) + (k0 & 31);
                const ulonglong2 uv = u2[ch];
#pragma unroll
                for (int b = 0; b < 4; ++b) {
                    const ulonglong2 hv = *(const ulonglong2*)(hp + 32 * b);
                    ffma2(acc[b], hv.x, uv.x);
                    ffma2(acc[b], hv.y, uv.y);
                }
            }
#pragma unroll
            for (int b = 0; b < 4; ++b)
                redA[(b * 4 + KQ) * 128 + col] = pairsum(acc[b]);
        }
        __syncthreads();
        if (tid < 128) {
            float si = 0, sf = 0, sg2 = 0, so = 0;
#pragma unroll
            for (int q = 0; q < 4; ++q) {
                const float* rq = redA + (ob * 4 + q) * 128;
                si  += rq[0  + ou];
                sf  += rq[32 + ou];
                sg2 += rq[64 + ou];
                so  += rq[96 + ou];
            }
            const float gi = sigf(piA + si);
            const float gf = sigf(pfA + sf);
            const float gg = tanh_fast(pgA + sg2);
            const float go = sigf(poA + so);
            cA = gf * cA + gi * gg;
            const float h = go * tanh_fast(cA);
            ObA[(size_t)t * HH] = h;
            if (t + 1 < TT) {
                stgA[cb * 128 + ob * 32 + ou] = h;
                asm volatile("bar.sync 1, 128;" ::: "memory");
                if (tid < 8) {
                    fence_async_proxy();
                    const uint32_t src  = smb + (STGA_OFF + cb * 128) * 4;
                    const uint32_t dstl = smb + (HBA_OFF + nb * 1024 + rank * 128) * 4;
                    const uint32_t lmb  = mbar0 + 8 * nb;
                    bulk_dsmem(mapa_u32(dstl, (uint32_t)tid), src, 512,
                               mapa_u32(lmb, (uint32_t)tid));
                }
            }
            piA = npi; pfA = npf; pgA = npg; poA = npo;
        }

        // ================= GROUP B =================
        if (tid < 128 && t + 1 < TT) {
            const float* pr = PbB + (size_t)(t + 1) * 1024;
            npi = pr[0]; npf = pr[256]; npg = pr[512]; npo = pr[768];
        }
        if (t > 0) {
            const uint32_t mb = mbar0 + 16 + 8 * cb;
            if (cb) { mbar_wait_acq(mb, phB1); phB1 ^= 1; }
            else    { mbar_wait_acq(mb, phB0); phB0 ^= 1; }
            if (tid == 0 && t + 2 < TT) mbar_arm_tx(mb, TX_STEP);
        }
        {
            const float* ha = hbB + cb * 1024;
            unsigned long long acc[4] = {0ull, 0ull, 0ull, 0ull};
#pragma unroll
            for (int ch = 0; ch < 16; ++ch) {
                const int k0 = KQ * 64 + 4 * ch;
                const float* hp = ha + ((k0 >> 5) << 7) + (k0 & 31);
                const ulonglong2 uv = u2[ch];
#pragma unroll
                for (int b = 0; b < 4; ++b) {
                    const ulonglong2 hv = *(const ulonglong2*)(hp + 32 * b);
                    ffma2(acc[b], hv.x, uv.x);
                    ffma2(acc[b], hv.y, uv.y);
                }
            }
#pragma unroll
            for (int b = 0; b < 4; ++b)
                redB[(b * 4 + KQ) * 128 + col] = pairsum(acc[b]);
        }
        __syncthreads();
        if (tid < 128) {
            float si = 0, sf = 0, sg2 = 0, so = 0;
#pragma unroll
            for (int q = 0; q < 4; ++q) {
                const float* rq = redB + (ob * 4 + q) * 128;
                si  += rq[0  + ou];
                sf  += rq[32 + ou];
                sg2 += rq[64 + ou];
                so  += rq[96 + ou];
            }
            const float gi = sigf(piB + si);
            const float gf = sigf(pfB + sf);
            const float gg = tanh_fast(pgB + sg2);
            const float go = sigf(poB + so);
            cB = gf * cB + gi * gg;
            const float h = go * tanh_fast(cB);
            ObB[(size_t)t * HH] = h;
            if (t + 1 < TT) {
                stgB[cb * 128 + ob * 32 + ou] = h;
                asm volatile("bar.sync 1, 128;" ::: "memory");
                if (tid < 8) {
                    fence_async_proxy();
                    const uint32_t src  = smb + (STGB_OFF + cb * 128) * 4;
                    const uint32_t dstl = smb + (HBB_OFF + nb * 1024 + rank * 128) * 4;
                    const uint32_t lmb  = mbar0 + 16 + 8 * nb;
                    bulk_dsmem(mapa_u32(dstl, (uint32_t)tid), src, 512,
                               mapa_u32(lmb, (uint32_t)tid));
                }
            }
            piB = npi; pfB = npf; pgB = npg; poB = npo;
        }
    }
    cluster_sync_();   // teardown safety
}

// ---------------------------------------------------------------------------
extern "C" void kernel_launch(void* const* d_in, const int* in_sizes, int n_in,
                              void* d_out, int out_size) {
    const float* X  = (const float*)d_in[0];
    const float* Wa = (const float*)d_in[1];
    const float* ba = (const float*)d_in[2];
    const float* Wl = (const float*)d_in[3];
    const float* Ul = (const float*)d_in[4];
    const float* bl = (const float*)d_in[5];
    float* out = (float*)d_out;
    float* out_xt  = out;                          // (B,Tm1,N)
    float* out_enc = out + (size_t)MM * NN;        // (B,Tm1,H)

    cudaFuncSetAttribute(k_lstm, cudaFuncAttributeMaxDynamicSharedMemorySize,
                         SMEM_BYTES);

    k_alpha<<<BB, 256>>>(X, Wa, ba);
    k_xtilde<<<(MM * NN / 4) / 256, 256>>>(X, out_xt);
    k_gemm<<<dim3(FH / 128, MM / 128), 256>>>(out_xt, Wl, bl);
    k_lstm<<<128, 512, SMEM_BYTES>>>(X, Ul, out_enc);
}

// round 13
// speedup vs baseline: 1.1666x; 1.1666x over previous
#include <cuda_runtime.h>
#include <cuda_bf16.h>
#include <cstdint>
#include <math.h>

// Fixed problem dims
#define BB   128
#define TT   255
#define NN   256
#define HH   256
#define FH   1024
#define MM   (BB*TT)          // 32640

// Static device scratch (no allocations allowed)
__device__ float g_alpha[BB * NN];
__device__ float g_P[(size_t)MM * FH];   // 133.7 MB

// ---------------------------------------------------------------------------
// helpers
// ---------------------------------------------------------------------------
__device__ __forceinline__ uint32_t smem_u32(const void* p) {
    uint32_t a;
    asm("{ .reg .u64 t; cvta.to.shared.u64 t, %1; cvt.u32.u64 %0, t; }"
        : "=r"(a) : "l"(p));
    return a;
}
__device__ __forceinline__ uint32_t mapa_u32(uint32_t addr, uint32_t rank) {
    uint32_t r;
    asm("mapa.shared::cluster.u32 %0, %1, %2;" : "=r"(r) : "r"(addr), "r"(rank));
    return r;
}
__device__ __forceinline__ uint32_t ctarank() {
    uint32_t r;
    asm("mov.u32 %0, %%cluster_ctarank;" : "=r"(r));
    return r;
}
__device__ __forceinline__ void cluster_sync_() {
    asm volatile("barrier.cluster.arrive.aligned;" ::: "memory");
    asm volatile("barrier.cluster.wait.aligned;" ::: "memory");
}
__device__ __forceinline__ void ffma2(unsigned long long& d,
                                      unsigned long long a,
                                      unsigned long long b) {
    asm("fma.rn.f32x2 %0, %1, %2, %0;" : "+l"(d) : "l"(a), "l"(b));
}
__device__ __forceinline__ float pairsum(unsigned long long v) {
    float lo, hi;
    asm("mov.b64 {%0,%1}, %2;" : "=f"(lo), "=f"(hi) : "l"(v));
    return lo + hi;
}
__device__ __forceinline__ unsigned long long pack2(float a) {
    unsigned long long d;
    asm("mov.b64 %0, {%1,%1};" : "=l"(d) : "f"(a));
    return d;
}
__device__ __forceinline__ unsigned long long packab(float a, float b) {
    unsigned long long d;
    asm("mov.b64 %0, {%1,%2};" : "=l"(d) : "f"(a), "f"(b));
    return d;
}
__device__ __forceinline__ void unpack2(unsigned long long v, float& lo, float& hi) {
    asm("mov.b64 {%0,%1}, %2;" : "=f"(lo), "=f"(hi) : "l"(v));
}
__device__ __forceinline__ void mbar_init(uint32_t mbar, uint32_t count) {
    asm volatile("mbarrier.init.shared.b64 [%0], %1;" :: "r"(mbar), "r"(count)
                 : "memory");
}
__device__ __forceinline__ void mbar_arm_tx(uint32_t mbar, uint32_t tx) {
    asm volatile("mbarrier.arrive.expect_tx.shared.b64 _, [%0], %1;"
                 :: "r"(mbar), "r"(tx) : "memory");
}
__device__ __forceinline__ void mbar_wait_acq(uint32_t mbar, uint32_t parity) {
    uint32_t done;
    asm volatile(
        "{\n\t.reg .pred P;\n\t"
        "mbarrier.try_wait.parity.acquire.cluster.shared::cta.b64 P, [%1], %2;\n\t"
        "selp.b32 %0, 1, 0, P;\n\t}"
        : "=r"(done) : "r"(mbar), "r"(parity) : "memory");
    while (!done) {
        asm volatile(
            "{\n\t.reg .pred P;\n\t"
            "mbarrier.try_wait.parity.acquire.cluster.shared::cta.b64 P, [%1], %2, 0x989680;\n\t"
            "selp.b32 %0, 1, 0, P;\n\t}"
            : "=r"(done) : "r"(mbar), "r"(parity) : "memory");
    }
}
__device__ __forceinline__ void st_async_f32(uint32_t raddr, float v,
                                             uint32_t rmbar) {
    asm volatile(
        "st.async.shared::cluster.mbarrier::complete_tx::bytes.b32 [%0], %1, [%2];"
        :: "r"(raddr), "r"(__float_as_uint(v)), "r"(rmbar) : "memory");
}
__device__ __forceinline__ float sigf(float x) {
    return __fdividef(1.0f, 1.0f + __expf(-x));
}
__device__ __forceinline__ float tanh_fast(float x) {
    float e = __expf(-2.0f * x);
    return __fdividef(1.0f - e, 1.0f + e);
}

// ---------------------------------------------------------------------------
// K1: alpha[b,n] = softmax_n( b_attn + sum_t X[b,t,n] * Wa[2H+t] )
// ---------------------------------------------------------------------------
__global__ __launch_bounds__(256) void k_alpha(const float* __restrict__ X,
                                               const float* __restrict__ Wa,
                                               const float* __restrict__ ba) {
    __shared__ float was[TT];
    __shared__ float red[256];
    const int b = blockIdx.x, n = threadIdx.x;
    if (n < TT) was[n] = Wa[2 * HH + n];
    __syncthreads();

    const float* xb = X + (size_t)b * TT * NN + n;
    float acc = ba[0];
#pragma unroll 5
    for (int t = 0; t < TT; ++t) acc = fmaf(xb[(size_t)t * NN], was[t], acc);

    red[n] = acc; __syncthreads();
    for (int s = 128; s > 0; s >>= 1) {
        if (n < s) red[n] = fmaxf(red[n], red[n + s]);
        __syncthreads();
    }
    const float mx = red[0]; __syncthreads();
    const float e = expf(acc - mx);
    red[n] = e; __syncthreads();
    for (int s = 128; s > 0; s >>= 1) {
        if (n < s) red[n] += red[n + s];
        __syncthreads();
    }
    g_alpha[b * NN + n] = e / red[0];
}

// ---------------------------------------------------------------------------
// K2: X_tilde = alpha * X  ->  d_out[0 : MM*NN)
// ---------------------------------------------------------------------------
__global__ __launch_bounds__(256) void k_xtilde(const float* __restrict__ X,
                                                float* __restrict__ out) {
    const int idx = blockIdx.x * 256 + threadIdx.x;          // < MM*NN/4
    const float4 x = ((const float4*)X)[idx];
    const int b   = idx / (TT * NN / 4);
    const int rem = idx - b * (TT * NN / 4);
    const int n4  = rem & (NN / 4 - 1);
    const float4 a = ((const float4*)g_alpha)[b * (NN / 4) + n4];
    float4 o;
    o.x = x.x * a.x; o.y = x.y * a.y; o.z = x.z * a.z; o.w = x.w * a.w;
    ((float4*)out)[idx] = o;
}

// ---------------------------------------------------------------------------
// K3: P = X_tilde @ W_lstm + b_lstm   (M=32640, Ncols=1024, K=256) fp32
// 128x128 tile, 256 threads, 8x8 microtile, fma.rn.f32x2,
// register double-buffered global loads.
// ---------------------------------------------------------------------------
__global__ __launch_bounds__(256) void k_gemm(const float* __restrict__ A,
                                              const float* __restrict__ W,
                                              const float* __restrict__ bias) {
    __shared__ float As[16 * 132];
    __shared__ float Bs[16 * 132];
    const int tx = threadIdx.x & 15;
    const int ty = threadIdx.x >> 4;
    const int m0 = blockIdx.y * 128;
    const int c0 = blockIdx.x * 128;

    unsigned long long acc2[8][4];
#pragma unroll
    for (int i = 0; i < 8; ++i)
#pragma unroll
        for (int j = 0; j < 4; ++j) acc2[i][j] = 0ull;

    float4 pa[2], pb[2];
#pragma unroll
    for (int i = 0; i < 2; ++i) {
        const int id = threadIdx.x + 256 * i;
        pa[i] = *(const float4*)(A + (size_t)(m0 + (id >> 2)) * 256 + 4 * (id & 3));
        pb[i] = *(const float4*)(W + (size_t)(id >> 5) * 1024 + c0 + 4 * (id & 31));
    }

    for (int kk0 = 0; kk0 < 256; kk0 += 16) {
#pragma unroll
        for (int i = 0; i < 2; ++i) {               // store staged tiles
            const int id = threadIdx.x + 256 * i;
            const int q = id & 3, row = id >> 2;
            As[(4 * q + 0) * 132 + row] = pa[i].x;
            As[(4 * q + 1) * 132 + row] = pa[i].y;
            As[(4 * q + 2) * 132 + row] = pa[i].z;
            As[(4 * q + 3) * 132 + row] = pa[i].w;
            const int c4 = id & 31, k = id >> 5;
            *(float4*)(Bs + k * 132 + 4 * c4) = pb[i];
        }
        __syncthreads();
        if (kk0 + 16 < 256) {                       // prefetch next tiles
#pragma unroll
            for (int i = 0; i < 2; ++i) {
                const int id = threadIdx.x + 256 * i;
                pa[i] = *(const float4*)(A + (size_t)(m0 + (id >> 2)) * 256 +
                                         kk0 + 16 + 4 * (id & 3));
                pb[i] = *(const float4*)(W + (size_t)(kk0 + 16 + (id >> 5)) * 1024 +
                                         c0 + 4 * (id & 31));
            }
        }
#pragma unroll
        for (int kk = 0; kk < 16; ++kk) {
            const float4 a0 = *(const float4*)(As + kk * 132 + 4 * ty);
            const float4 a1 = *(const float4*)(As + kk * 132 + 64 + 4 * ty);
            const ulonglong2 bq0 = *(const ulonglong2*)(Bs + kk * 132 + 4 * tx);
            const ulonglong2 bq1 = *(const ulonglong2*)(Bs + kk * 132 + 64 + 4 * tx);
            const float av[8] = {a0.x, a0.y, a0.z, a0.w, a1.x, a1.y, a1.z, a1.w};
#pragma unroll
            for (int i = 0; i < 8; ++i) {
                const unsigned long long ad = pack2(av[i]);
                ffma2(acc2[i][0], ad, bq0.x);
                ffma2(acc2[i][1], ad, bq0.y);
                ffma2(acc2[i][2], ad, bq1.x);
                ffma2(acc2[i][3], ad, bq1.y);
            }
        }
        __syncthreads();
    }
#pragma unroll
    for (int i = 0; i < 8; ++i) {
        const int row = (i < 4) ? (4 * ty + i) : (64 + 4 * ty + (i - 4));
        float* p = g_P + (size_t)(m0 + row) * 1024 + c0;
        float4 o0, o1;
        float lo, hi;
        unpack2(acc2[i][0], lo, hi);
        o0.x = lo + bias[c0 + 4 * tx + 0];
        o0.y = hi + bias[c0 + 4 * tx + 1];
        unpack2(acc2[i][1], lo, hi);
        o0.z = lo + bias[c0 + 4 * tx + 2];
        o0.w = hi + bias[c0 + 4 * tx + 3];
        unpack2(acc2[i][2], lo, hi);
        o1.x = lo + bias[c0 + 64 + 4 * tx + 0];
        o1.y = hi + bias[c0 + 64 + 4 * tx + 1];
        unpack2(acc2[i][3], lo, hi);
        o1.z = lo + bias[c0 + 64 + 4 * tx + 2];
        o1.w = hi + bias[c0 + 64 + 4 * tx + 3];
        *(float4*)(p + 4 * tx) = o0;
        *(float4*)(p + 64 + 4 * tx) = o1;
    }
}

// ---------------------------------------------------------------------------
// K4 v8: LSTM recurrence = proven v5 datapath + SINGLE-THREAD cluster-acquire
// wait (A/B test: replaces 16 per-warp cluster acquires with 1 + syncthreads)
// + conflict-free reduction layout + direct gmem->register U load.
// 16 clusters x 8 CTAs, 512 threads, 4-way k-split, U in registers,
// broadcast h loads, h exchange via st.async + tx-counted mbarriers.
// ---------------------------------------------------------------------------
#define PITCH 260
#define HB_STRIDE (8 * PITCH)                // 2080 floats per h buffer
#define HB_OFF    0                          // 2 x 2080
#define RED_OFF   (2 * HB_STRIDE)            // 4160: red[2][8][512]
#define MBAR_OFF  (RED_OFF + 2 * 8 * 512)    // 12352: 2 x u64
#define SMEM_FLOATS (MBAR_OFF + 4)
#define SMEM_BYTES  (SMEM_FLOATS * 4)        // 49,424 B
#define TX_PER_STEP (8 * 256 * 4)            // 8192 B into each CTA per step

__global__ __launch_bounds__(512, 1) __cluster_dims__(8, 1, 1)
void k_lstm(const float* __restrict__ X, const float* __restrict__ U,
            float* __restrict__ out_enc) {
    extern __shared__ float sm[];
    float* hb   = sm + HB_OFF;               // 2 x [8 batches][pitch 260]
    float* redb = sm + RED_OFF;              // [2][8 batches][512]

    const int rank = (int)ctarank();                 // 0..7
    const int b0   = (blockIdx.x >> 3) * 8;
    const int tid  = threadIdx.x;
    // compute role
    const int col  = tid & 127;                      // gate-col 0..127
    const int KQ   = tid >> 7;                       // k quarter 0..3
    // owner role (tid < 256)
    const int ob   = tid >> 5;                       // batch 0..7
    const int ou   = tid & 31;                       // unit 0..31
    const int jglob = rank * 32 + ou;

    const uint32_t smb = smem_u32(sm);
    const uint32_t mbar0 = smb + MBAR_OFF * 4;       // mbar[i] at +8*i

    // ---- U slice direct to registers (coalesced; verified in R12)
    const int g  = col >> 5, jr = col & 31;
    const int gcol = g * 256 + rank * 32 + jr;
    ulonglong2 u2[16];
    {
        const float* Ub = U + (size_t)(KQ * 64) * 1024 + gcol;
#pragma unroll
        for (int i = 0; i < 16; ++i) {
            const float a0 = Ub[(4 * i + 0) * 1024];
            const float a1 = Ub[(4 * i + 1) * 1024];
            const float a2 = Ub[(4 * i + 2) * 1024];
            const float a3 = Ub[(4 * i + 3) * 1024];
            u2[i].x = packab(a0, a1);
            u2[i].y = packab(a2, a3);
        }
    }

    // ---- init h buffer 0 (h0 = c0 = X[b,0,0]) and mbarriers
    for (int idx = tid; idx < 8 * 256; idx += 512) {
        const int b = idx >> 8, k = idx & 255;
        hb[b * PITCH + k] = X[(size_t)(b0 + b) * TT * NN];
    }
    if (tid == 0) {
        mbar_init(mbar0 + 0, 1);
        mbar_init(mbar0 + 8, 1);
        mbar_arm_tx(mbar0 + 0, TX_PER_STEP);   // first waited at t=2
        mbar_arm_tx(mbar0 + 8, TX_PER_STEP);   // first waited at t=1
    }
    __syncthreads();
    float c = (tid < 256) ? X[(size_t)(b0 + ob) * TT * NN] : 0.0f;
    cluster_sync_();   // mbarriers + buffer0 visible cluster-wide (once)

    const float* Pb = g_P + ((size_t)(b0 + ob) * TT) * 1024 + jglob;
    float* Ob = out_enc + ((size_t)(b0 + ob) * TT) * HH + jglob;
    float pi = 0.f, pf = 0.f, pg = 0.f, po = 0.f;
    if (tid < 256) { pi = Pb[0]; pf = Pb[256]; pg = Pb[512]; po = Pb[768]; }

    uint32_t ph0 = 0, ph1 = 0;

    for (int t = 0; t < TT; ++t) {
        const int cb = t & 1;
        // prefetch next-step P before the wait (DRAM latency overlaps barrier)
        float npi = 0.f, npf = 0.f, npg = 0.f, npo = 0.f;
        if (tid < 256 && t + 1 < TT) {
            const float* pr = Pb + (size_t)(t + 1) * 1024;
            npi = pr[0]; npf = pr[256]; npg = pr[512]; npo = pr[768];
        }
        if (t > 0) {
            // SINGLE-THREAD cluster-acquire wait; CTA released by syncthreads.
            if (tid == 0) {
                const uint32_t mb = mbar0 + 8 * cb;
                if (cb) { mbar_wait_acq(mb, ph1); ph1 ^= 1; }
                else    { mbar_wait_acq(mb, ph0); ph0 ^= 1; }
                if (t + 2 < TT) mbar_arm_tx(mb, TX_PER_STEP);
            }
            __syncthreads();
        }

        const float* hc = hb + cb * HB_STRIDE + KQ * 64;
        unsigned long long acc[8];
#pragma unroll
        for (int b = 0; b < 8; ++b) acc[b] = 0ull;

#pragma unroll
        for (int ch = 0; ch < 16; ++ch) {
            const ulonglong2 uv = u2[ch];
#pragma unroll
            for (int b = 0; b < 8; ++b) {
                const ulonglong2 hv = *(const ulonglong2*)(hc + b * PITCH + 4 * ch);
                ffma2(acc[b], hv.x, uv.x);
                ffma2(acc[b], hv.y, uv.y);
            }
        }

        // conflict-free reduction stores: red[cb][b][KQ*128 + col]
        float* rw = redb + cb * 4096 + KQ * 128 + col;
#pragma unroll
        for (int b = 0; b < 8; ++b) rw[b * 512] = pairsum(acc[b]);
        __syncthreads();

        if (tid < 256) {
            // owner phase: combine 4 k-quarter partials (stride-1 reads)
            const float* rq = redb + cb * 4096 + ob * 512;
            float si = 0.f, sf = 0.f, sg2 = 0.f, so = 0.f;
#pragma unroll
            for (int q = 0; q < 4; ++q) {
                const float* r2 = rq + q * 128;
                si  += r2[0  + ou];
                sf  += r2[32 + ou];
                sg2 += r2[64 + ou];
                so  += r2[96 + ou];
            }
            const float gi = sigf(pi + si);
            const float gf = sigf(pf + sf);
            const float gg = tanh_fast(pg + sg2);
            const float go = sigf(po + so);
            c = gf * c + gi * gg;
            const float h = go * tanh_fast(c);

            Ob[(size_t)t * HH] = h;

            if (t + 1 < TT) {
                const int nb = 1 - cb;
                const uint32_t laddr = smb +
                    (HB_OFF + nb * HB_STRIDE + ob * PITCH + jglob) * 4;
                const uint32_t lmbar = mbar0 + 8 * nb;
#pragma unroll
                for (int r2i = 0; r2i < 8; ++r2i) {
                    const uint32_t ra2 = mapa_u32(laddr, (uint32_t)r2i);
                    const uint32_t rm2 = mapa_u32(lmbar, (uint32_t)r2i);
                    st_async_f32(ra2, h, rm2);
                }
            }
            pi = npi; pf = npf; pg = npg; po = npo;
        }
    }
    cluster_sync_();   // teardown safety
}

// ---------------------------------------------------------------------------
extern "C" void kernel_launch(void* const* d_in, const int* in_sizes, int n_in,
                              void* d_out, int out_size) {
    const float* X  = (const float*)d_in[0];
    const float* Wa = (const float*)d_in[1];
    const float* ba = (const float*)d_in[2];
    const float* Wl = (const float*)d_in[3];
    const float* Ul = (const float*)d_in[4];
    const float* bl = (const float*)d_in[5];
    float* out = (float*)d_out;
    float* out_xt  = out;                          // (B,Tm1,N)
    float* out_enc = out + (size_t)MM * NN;        // (B,Tm1,H)

    cudaFuncSetAttribute(k_lstm, cudaFuncAttributeMaxDynamicSharedMemorySize,
                         SMEM_BYTES);

    k_alpha<<<BB, 256>>>(X, Wa, ba);
    k_xtilde<<<(MM * NN / 4) / 256, 256>>>(X, out_xt);
    k_gemm<<<dim3(FH / 128, MM / 128), 256>>>(out_xt, Wl, bl);
    k_lstm<<<128, 512, SMEM_BYTES>>>(X, Ul, out_enc);
}